// round 4
// baseline (speedup 1.0000x reference)
#include <cuda_runtime.h>
#include <cstdint>

#define S_LEN  2048
#define TB     16
#define NHEAD  4
#define NPOS   12
#define VBITS  10
#define OBITS  12
#define WARPS_PER_BLK 16   // one warp per position, 512 threads/block, 128 blocks

// Inputs (metadata order):
//  0: tokens       (S, 16)        int32  (0/1 bits)
//  1: route_table  (H, 1<<24)     int32  (0/1)
//  2: value_table  (H, 16, 1024)  float32
//  3: output_table (16, 4096)     float32
//  4: conns_value  (H, 16, 10)    int32  in [0, 28)
//  5: conns_out    (16, 12)       int32  in [0, 64)
// Output: (S, 16) float32

__global__ __launch_bounds__(WARPS_PER_BLK * 32)
void poa_kernel(const int*   __restrict__ tokens,
                const int*   __restrict__ route_table,
                const float* __restrict__ value_table,
                const float* __restrict__ output_table,
                const int*   __restrict__ conns_value,
                const int*   __restrict__ conns_out,
                float*       __restrict__ out)
{
    const int tid  = threadIdx.x;
    const int lane = tid & 31;
    const int wid  = tid >> 5;
    const int i    = blockIdx.x * WARPS_PER_BLK + wid;   // position

    // Lane role for value/output stages: lane<16 -> heads {0,2}, lane>=16 -> {1,3}
    const bool hiA = (lane & 16) != 0;
    const int  b   = lane & 15;
    const int  hA  = hiA ? 1 : 0;
    const int  hB  = hA + 2;

    // ---- independent loads, issued up front (no barriers anywhere) ----

    // (a) per-lane connection rows straight to registers (L1-resident)
    int cvA[VBITS], cvB[VBITS];
    {
        const int* pA = conns_value + (hA * TB + b) * VBITS;
        const int* pB = conns_value + (hB * TB + b) * VBITS;
        #pragma unroll
        for (int k = 0; k < VBITS; k++) { cvA[k] = pA[k]; cvB[k] = pB[k]; }
    }
    int co[OBITS];
    {
        const int* pO = conns_out + b * OBITS;   // only lanes<16 use it
        #pragma unroll
        for (int k = 0; k < OBITS; k++) co[k] = pO[k];
    }

    // (b) candidate token rows 0..7: 8 rows x 16 ints = 32 int4, one per lane.
    //     lane = row*4 + c ; nibble covers token bits 4c..4c+3 of that row.
    unsigned rowmask;
    {
        int4 t4 = ((const int4*)tokens)[lane];
        unsigned nib = (unsigned)(t4.x > 0)
                     | ((unsigned)(t4.y > 0) << 1)
                     | ((unsigned)(t4.z > 0) << 2)
                     | ((unsigned)(t4.w > 0) << 3);
        rowmask = nib << (4 * (lane & 3));
    }

    // (c) route probe: lanes (h = lane>>3, j = lane&7)
    const int h0 = lane >> 3;
    const int jl = lane & 7;
    int rv = route_table[(h0 << 24) | (i << NPOS) | jl];

    // finish token packing while route load is in flight
    rowmask |= __shfl_xor_sync(0xffffffffu, rowmask, 1);
    rowmask |= __shfl_xor_sync(0xffffffffu, rowmask, 2);
    // now every lane in a group-of-4 holds the 16-bit mask of row (lane>>2)

    // ---- 1) j_first per head ----
    unsigned m = __ballot_sync(0xffffffffu, rv > 0);

    int  j0v = 0, j1v = 0, j2v = 0, j3v = 0;
    bool a0 = false, a1 = false, a2 = false, a3 = false;

    #define FIND_J(H, JV, AV)                                                      \
    {                                                                              \
        unsigned mh = (m >> (8 * (H))) & 0xffu;                                    \
        if (mh) { JV = __ffs(mh) - 1; AV = true; }                                 \
        else {                                                                     \
            const int base = ((H) << 24) | (i << NPOS);                            \
            for (int js = 8; js < S_LEN; js += 32) {                               \
                int vv = route_table[base + js + lane];                            \
                unsigned mm = __ballot_sync(0xffffffffu, vv > 0);                  \
                if (mm) { JV = js + __ffs(mm) - 1; AV = true; break; }             \
            }                                                                      \
        }                                                                          \
    }
    FIND_J(0, j0v, a0)
    FIND_J(1, j1v, a1)
    FIND_J(2, j2v, a2)
    FIND_J(3, j3v, a3)
    #undef FIND_J

    // ---- 2) token mask per head: fast shfl from preloaded rows, rare fallback ----
    #define TOKMASK(JV, TM)                                                        \
    {                                                                              \
        if ((JV) < 8) {                                                            \
            TM = __shfl_sync(0xffffffffu, rowmask, (JV) << 2) & 0xffffu;           \
        } else {                                                                   \
            int tv = (lane < TB) ? tokens[(JV) * TB + lane] : 0;                   \
            TM = __ballot_sync(0xffffffffu, tv > 0) & 0xffffu;                     \
        }                                                                          \
    }
    unsigned t0, t1, t2, t3;
    TOKMASK(j0v, t0)
    TOKMASK(j1v, t1)
    TOKMASK(j2v, t2)
    TOKMASK(j3v, t3)
    #undef TOKMASK

    // vin mask per head: bits 0..15 tokens, bits 16..27 pos bits (MSB-first pack)
    unsigned v0 = t0 | ((__brev((unsigned)j0v) >> 4) & 0x0fff0000u);
    unsigned v1 = t1 | ((__brev((unsigned)j1v) >> 4) & 0x0fff0000u);
    unsigned v2 = t2 | ((__brev((unsigned)j2v) >> 4) & 0x0fff0000u);
    unsigned v3 = t3 | ((__brev((unsigned)j3v) >> 4) & 0x0fff0000u);

    const unsigned vA = hiA ? v1 : v0;
    const unsigned vB = hiA ? v3 : v2;
    const bool     aA = hiA ? a1 : a0;
    const bool     aB = hiA ? a3 : a2;

    // ---- 3) value lookups: this lane covers (hA,b) and (hB,b) ----
    int vaA = 0, vaB = 0;
    #pragma unroll
    for (int k = 0; k < VBITS; k++) {
        vaA = (vaA << 1) | (int)((vA >> cvA[k]) & 1u);
        vaB = (vaB << 1) | (int)((vB >> cvB[k]) & 1u);
    }
    float valA = value_table[(hA * TB + b) * (1 << VBITS) + vaA];
    float valB = value_table[(hB * TB + b) * (1 << VBITS) + vaB];
    bool c1 = aA && (valA > 0.5f);
    bool c2 = aB && (valB > 0.5f);

    unsigned clo = __ballot_sync(0xffffffffu, c1);  // head0 bits 0-15, head1 16-31
    unsigned chi = __ballot_sync(0xffffffffu, c2);  // head2 bits 0-15, head3 16-31
    unsigned long long comb = (unsigned long long)clo
                            | ((unsigned long long)chi << 32);

    // ---- 4) output lookup: lanes 0-15 ----
    if (lane < TB) {
        int oa = 0;
        #pragma unroll
        for (int k = 0; k < OBITS; k++) oa = (oa << 1) | (int)((comb >> co[k]) & 1ull);
        out[i * TB + lane] = output_table[lane * (1 << OBITS) + oa];
    }
}

extern "C" void kernel_launch(void* const* d_in, const int* in_sizes, int n_in,
                              void* d_out, int out_size)
{
    const int*   tokens       = (const int*)  d_in[0];
    const int*   route_table  = (const int*)  d_in[1];
    const float* value_table  = (const float*)d_in[2];
    const float* output_table = (const float*)d_in[3];
    const int*   conns_value  = (const int*)  d_in[4];
    const int*   conns_out    = (const int*)  d_in[5];
    float*       out          = (float*)      d_out;

    poa_kernel<<<S_LEN / WARPS_PER_BLK, WARPS_PER_BLK * 32>>>(
        tokens, route_table, value_table, output_table,
        conns_value, conns_out, out);
}

// round 5
// speedup vs baseline: 1.2947x; 1.2947x over previous
#include <cuda_runtime.h>
#include <cstdint>

#define S_LEN  2048
#define TB     16
#define NHEAD  4
#define NPOS   12
#define VBITS  10
#define OBITS  12
#define WARPS_PER_BLK 16   // one warp per position, 512 threads/block, 128 blocks

// Inputs (metadata order):
//  0: tokens       (S, 16)        int32  (0/1 bits)
//  1: route_table  (H, 1<<24)     int32  (0/1)
//  2: value_table  (H, 16, 1024)  float32
//  3: output_table (16, 4096)     float32
//  4: conns_value  (H, 16, 10)    int32  in [0, 28)
//  5: conns_out    (16, 12)       int32  in [0, 64)
// Output: (S, 16) float32

__global__ __launch_bounds__(WARPS_PER_BLK * 32)
void poa_kernel(const int*   __restrict__ tokens,
                const int*   __restrict__ route_table,
                const float* __restrict__ value_table,
                const float* __restrict__ output_table,
                const int*   __restrict__ conns_value,
                const int*   __restrict__ conns_out,
                float*       __restrict__ out)
{
    // Conn tables staged in shared (coalesced int4 preload). cv=640, co=192 ints.
    __shared__ __align__(16) int s_cv[NHEAD * TB * VBITS];
    __shared__ __align__(16) int s_co[TB * OBITS];

    const int tid  = threadIdx.x;
    const int lane = tid & 31;
    const int wid  = tid >> 5;
    const int i    = blockIdx.x * WARPS_PER_BLK + wid;   // position

    // ---- independent front-loaded work (all issued before any dependency) ----

    // (a) coalesced conns preload: 160 + 48 int4 over 512 threads.
    if (tid < NHEAD * TB * VBITS / 4)
        ((int4*)s_cv)[tid] = ((const int4*)conns_value)[tid];
    else if (tid < NHEAD * TB * VBITS / 4 + TB * OBITS / 4) {
        int k = tid - NHEAD * TB * VBITS / 4;
        ((int4*)s_co)[k] = ((const int4*)conns_out)[k];
    }

    // (b) candidate token rows 0..7: 8 rows x 16 ints = 32 int4, one per lane.
    //     lane = row*4 + c ; nibble covers token bits 4c..4c+3 of row (lane>>2).
    unsigned rowmask;
    {
        int4 t4 = ((const int4*)tokens)[lane];
        unsigned nib = (unsigned)(t4.x > 0)
                     | ((unsigned)(t4.y > 0) << 1)
                     | ((unsigned)(t4.z > 0) << 2)
                     | ((unsigned)(t4.w > 0) << 3);
        rowmask = nib << (4 * (lane & 3));
    }

    // (c) route probe: lanes (h = lane>>3, j = lane&7) cover first 8 j's per head
    const int h0 = lane >> 3;
    const int jl = lane & 7;
    int rv = route_table[(h0 << 24) | (i << NPOS) | jl];

    // finish token packing while the route load is in flight
    rowmask |= __shfl_xor_sync(0xffffffffu, rowmask, 1);
    rowmask |= __shfl_xor_sync(0xffffffffu, rowmask, 2);
    // every lane of a group-of-4 now holds the 16-bit token mask of row (lane>>2)

    // ---- 1) j_first per head ----
    unsigned m = __ballot_sync(0xffffffffu, rv > 0);

    int  j0v = 0, j1v = 0, j2v = 0, j3v = 0;
    bool a0 = false, a1 = false, a2 = false, a3 = false;

    #define FIND_J(H, JV, AV)                                                      \
    {                                                                              \
        unsigned mh = (m >> (8 * (H))) & 0xffu;                                    \
        if (mh) { JV = __ffs(mh) - 1; AV = true; }                                 \
        else {                                                                     \
            const int base = ((H) << 24) | (i << NPOS);                            \
            for (int js = 8; js < S_LEN; js += 32) {                               \
                int vv = route_table[base + js + lane];                            \
                unsigned mm = __ballot_sync(0xffffffffu, vv > 0);                  \
                if (mm) { JV = js + __ffs(mm) - 1; AV = true; break; }             \
            }                                                                      \
        }                                                                          \
    }
    FIND_J(0, j0v, a0)
    FIND_J(1, j1v, a1)
    FIND_J(2, j2v, a2)
    FIND_J(3, j3v, a3)
    #undef FIND_J

    // ---- 2) token mask per head: shfl from prefetched rows (j<8 w.p. 99.6%) ----
    #define TOKMASK(JV, TM)                                                        \
    {                                                                              \
        if ((JV) < 8) {                                                            \
            TM = __shfl_sync(0xffffffffu, rowmask, (JV) << 2) & 0xffffu;           \
        } else {                                                                   \
            int tv = (lane < TB) ? tokens[(JV) * TB + lane] : 0;                   \
            TM = __ballot_sync(0xffffffffu, tv > 0) & 0xffffu;                     \
        }                                                                          \
    }
    unsigned t0, t1, t2, t3;
    TOKMASK(j0v, t0)
    TOKMASK(j1v, t1)
    TOKMASK(j2v, t2)
    TOKMASK(j3v, t3)
    #undef TOKMASK

    // vin mask per head: bits 0..15 tokens, bits 16..27 pos bits (MSB-first pack)
    unsigned v0 = t0 | ((__brev((unsigned)j0v) >> 4) & 0x0fff0000u);
    unsigned v1 = t1 | ((__brev((unsigned)j1v) >> 4) & 0x0fff0000u);
    unsigned v2 = t2 | ((__brev((unsigned)j2v) >> 4) & 0x0fff0000u);
    unsigned v3 = t3 | ((__brev((unsigned)j3v) >> 4) & 0x0fff0000u);

    // lane role: lane<16 -> heads {0,2}, lane>=16 -> {1,3}
    const bool hiA = (lane & 16) != 0;
    const int  b   = lane & 15;
    const int  hA  = hiA ? 1 : 0;
    const int  hB  = hA + 2;

    const unsigned vA = hiA ? v1 : v0;
    const unsigned vB = hiA ? v3 : v2;
    const bool     aA = hiA ? a1 : a0;
    const bool     aB = hiA ? a3 : a2;

    __syncthreads();  // conns tables ready (preload long since landed)

    // ---- 3) value lookups: this lane covers (hA,b) and (hB,b) ----
    int vaA = 0, vaB = 0;
    const int* cvA = &s_cv[(hA * TB + b) * VBITS];
    const int* cvB = &s_cv[(hB * TB + b) * VBITS];
    #pragma unroll
    for (int k = 0; k < VBITS; k++) {
        vaA = (vaA << 1) | (int)((vA >> cvA[k]) & 1u);
        vaB = (vaB << 1) | (int)((vB >> cvB[k]) & 1u);
    }
    float valA = value_table[(hA * TB + b) * (1 << VBITS) + vaA];
    float valB = value_table[(hB * TB + b) * (1 << VBITS) + vaB];
    bool c1 = aA && (valA > 0.5f);
    bool c2 = aB && (valB > 0.5f);

    unsigned clo = __ballot_sync(0xffffffffu, c1);  // head0 bits 0-15, head1 16-31
    unsigned chi = __ballot_sync(0xffffffffu, c2);  // head2 bits 0-15, head3 16-31
    unsigned long long comb = (unsigned long long)clo
                            | ((unsigned long long)chi << 32);

    // ---- 4) output lookup: lanes 0-15 ----
    if (lane < TB) {
        const int* co = &s_co[lane * OBITS];
        int oa = 0;
        #pragma unroll
        for (int k = 0; k < OBITS; k++) oa = (oa << 1) | (int)((comb >> co[k]) & 1ull);
        out[i * TB + lane] = output_table[lane * (1 << OBITS) + oa];
    }
}

extern "C" void kernel_launch(void* const* d_in, const int* in_sizes, int n_in,
                              void* d_out, int out_size)
{
    const int*   tokens       = (const int*)  d_in[0];
    const int*   route_table  = (const int*)  d_in[1];
    const float* value_table  = (const float*)d_in[2];
    const float* output_table = (const float*)d_in[3];
    const int*   conns_value  = (const int*)  d_in[4];
    const int*   conns_out    = (const int*)  d_in[5];
    float*       out          = (float*)      d_out;

    poa_kernel<<<S_LEN / WARPS_PER_BLK, WARPS_PER_BLK * 32>>>(
        tokens, route_table, value_table, output_table,
        conns_value, conns_out, out);
}